// round 12
// baseline (speedup 1.0000x reference)
#include <cuda_runtime.h>
#include <math.h>

// Problem constants
#define NB 8
#define NK 1024
#define NL 1024
#define ND 1024
#define NO 6
#define NE 128

// Scratch (tiny): everything l-independent
__device__ __align__(16) float g_S [NB*NO*NE];   // raw vote sum   [b,o,e]
__device__ __align__(16) float g_Wv[NB*NO*ND];   // W @ v          [b,o,d]
__device__ __align__(16) float g_a [NB*NK*NO];   // logits         [b,k,o]
__device__ __align__(16) float g_p [NB*NK*NO];   // probs          [b,k,o]
__device__ __align__(16) float g_pu[NB*NO*ND];   // p^T @ u        [b,o,d]
__device__ int g_mask_is_u8;                     // mask dtype flag

// ---------------------------------------------------------------------------
// Prolog: zero g_pu & g_S, detect mask dtype.
__global__ void k_prolog(const unsigned char* __restrict__ mraw) {
    int i = blockIdx.x * 256 + threadIdx.x;
    if (i < NB*NO*ND) g_pu[i] = 0.f;
    if (i < NB*NO*NE) g_S[i]  = 0.f;
    if (blockIdx.x == 0 && threadIdx.x == 0) {
        int u8 = 0;
        for (int j = 0; j < 256; j++)
            if ((j & 3) != 0 && mraw[j] != 0) u8 = 1;
        g_mask_is_u8 = u8;
    }
}

__device__ __forceinline__ int mask_at(const unsigned char* mraw, size_t idx) {
    if (g_mask_is_u8) return mraw[idx] != 0;
    return ((const int*)mraw)[idx] != 0;
}

// ---------------------------------------------------------------------------
// Iteration-0 shortcut: p0 = 1/6 uniform, so pu0[b,o,d] = (1/6)*sum_k u —
// o-independent. colsum into g_pu[b][0][:]. float4: thread owns 4 d's.
// grid (NB, 32) = 256 blocks, block 256; k-chunk = 32.
__global__ void k_colsum(const float* __restrict__ u) {
    int b  = blockIdx.x;
    int kb = blockIdx.y * 32;
    const float4* up4 = (const float4*)(u + ((size_t)b * NK + kb) * ND) + threadIdx.x;
    float4 acc = make_float4(0.f, 0.f, 0.f, 0.f);
#pragma unroll 8
    for (int kk = 0; kk < 32; kk++) {
        float4 uv = up4[kk * (ND / 4)];
        acc.x += uv.x; acc.y += uv.y; acc.z += uv.z; acc.w += uv.w;
    }
    float* dst = &g_pu[(size_t)b * NO * ND + threadIdx.x * 4];
    atomicAdd(dst + 0, acc.x);
    atomicAdd(dst + 1, acc.y);
    atomicAdd(dst + 2, acc.z);
    atomicAdd(dst + 3, acc.w);
}

// ---------------------------------------------------------------------------
// S[b,o,e] += sum_{d in 16-chunk} pu[b,o,d] * W[o,d,e] for all 8 b at once.
// FIRST: read o-independent colsum (o=0 row) scaled by 1/6.
// grid (NO, ND/16), block 128.
template <int FIRST>
__global__ void k_S(const float* __restrict__ W) {
    __shared__ float spu[NB][16];
    int o  = blockIdx.x;
    int dc = blockIdx.y * 16;
    int e  = threadIdx.x;

    {   // 128 threads load exactly 128 entries
        int b = threadIdx.x >> 4, dd = threadIdx.x & 15;
        float v = FIRST ? g_pu[(size_t)b * NO * ND + dc + dd] * (1.f / 6.f)
                        : g_pu[((size_t)b * NO + o) * ND + dc + dd];
        spu[b][dd] = v;
    }
    __syncthreads();

    float acc[NB];
#pragma unroll
    for (int b = 0; b < NB; b++) acc[b] = 0.f;

    const float* Wo = W + ((size_t)o * ND + dc) * NE + e;
#pragma unroll
    for (int dd = 0; dd < 16; dd++) {
        float w = Wo[(size_t)dd * NE];
#pragma unroll
        for (int b = 0; b < NB; b++) acc[b] += spu[b][dd] * w;
    }
#pragma unroll
    for (int b = 0; b < NB; b++)
        atomicAdd(&g_S[((size_t)b * NO + o) * NE + e], acc[b]);
}

// ---------------------------------------------------------------------------
// Fused squash + Wv: v = squash(S) per-block, then Wv[b,o,d] =
// sum_e W[o,d,e]*v[b,o,e] for all 8 b. float4 W + v loads.
// Also zeroes g_pu for the next k_apu (768 blocks x 64 floats).
// grid (NO, ND/8), block 256 = 8 warps (warp = one d)
__global__ void k_WvSq(const float* __restrict__ W) {
    __shared__ __align__(16) float sv[NB][NE];   // 4 KB
    __shared__ float sfac[NB];
    int o = blockIdx.x;
    int wid = threadIdx.x >> 5, lane = threadIdx.x & 31;

    // zero g_pu slice: 49152 / 768 blocks = 64 floats per block
    {
        int slice = blockIdx.x * (ND / 8) + blockIdx.y;   // 0..767
        if (threadIdx.x < 64) g_pu[(size_t)slice * 64 + threadIdx.x] = 0.f;
    }

    for (int i = threadIdx.x; i < NB * NE; i += 256)
        sv[i >> 7][i & 127] = g_S[((size_t)(i >> 7) * NO + o) * NE + (i & 127)];
    __syncthreads();

    // warp w computes squash factor for b=w
    {
        float sq = 0.f;
#pragma unroll
        for (int j = 0; j < 4; j++) {
            float x = sv[wid][lane + 32 * j];
            sq += x * x;
        }
#pragma unroll
        for (int off = 16; off; off >>= 1) sq += __shfl_xor_sync(0xffffffffu, sq, off);
        if (lane == 0) sfac[wid] = sq / (1.f + sq) / (sqrtf(sq) + 1e-8f);
    }
    __syncthreads();
    for (int i = threadIdx.x; i < NB * NE; i += 256)
        sv[i >> 7][i & 127] *= sfac[i >> 7];
    __syncthreads();

    int d = blockIdx.y * 8 + wid;
    const float4* Wrow4 = (const float4*)(W + ((size_t)o * ND + d) * NE);
    float4 wv = Wrow4[lane];

#pragma unroll
    for (int b = 0; b < NB; b++) {
        float4 vv = ((const float4*)sv[b])[lane];
        float s = wv.x * vv.x + wv.y * vv.y + wv.z * vv.z + wv.w * vv.w;
#pragma unroll
        for (int off = 16; off; off >>= 1) s += __shfl_xor_sync(0xffffffffu, s, off);
        if (lane == 0) g_Wv[((size_t)b * NO + o) * ND + d] = s;
    }
}

// ---------------------------------------------------------------------------
// Fused agreement + softmax + pu-accumulation (float4 loads):
//  phase 1: a[b,k,o] (+)= sum_d u[b,k,d]*Wv[b,o,d]; p = masked softmax
//  phase 2: pu[b,o,d] += sum_{k in block} p[k,o]*u[b,k,d]  (u hot in L1/L2)
// Also zeroes g_S slices for the next k_S.
// grid (NB, NK/16) = 512 blocks, block 256 = 8 warps, each warp does 2 k's.
template <int ACCUM>
__global__ void k_apu(const float* __restrict__ u,
                      const unsigned char* __restrict__ mraw) {
    __shared__ __align__(16) float sWv[NO * ND];  // 24 KB
    __shared__ float sp[16][NO];
    int b  = blockIdx.x;
    int kb = blockIdx.y * 16;

    // zero g_S slice: 6144 / 512 blocks = 12 floats each
    {
        int slice = blockIdx.x * 64 + blockIdx.y;   // 0..511
        if (threadIdx.x < 12) g_S[(size_t)slice * 12 + threadIdx.x] = 0.f;
    }

    for (int i = threadIdx.x; i < NO * ND; i += 256)
        sWv[i] = g_Wv[(size_t)b * NO * ND + i];
    __syncthreads();

    int warp = threadIdx.x >> 5, lane = threadIdx.x & 31;

    for (int ki = 0; ki < 2; ki++) {
        int k = kb + warp * 2 + ki;
        const float4* urow4 = (const float4*)(u + ((size_t)b * NK + k) * ND);
        float av[NO];
#pragma unroll
        for (int o = 0; o < NO; o++) av[o] = 0.f;
#pragma unroll
        for (int j = 0; j < 8; j++) {
            float4 uv = urow4[lane + 32 * j];
            int d0 = 4 * lane + 128 * j;
#pragma unroll
            for (int o = 0; o < NO; o++) {
                float4 wv = *(const float4*)&sWv[o * ND + d0];
                av[o] += uv.x * wv.x + uv.y * wv.y + uv.z * wv.z + uv.w * wv.w;
            }
        }
#pragma unroll
        for (int off = 16; off; off >>= 1) {
#pragma unroll
            for (int o = 0; o < NO; o++)
                av[o] += __shfl_xor_sync(0xffffffffu, av[o], off);
        }
        if (lane == 0) {
            size_t base = ((size_t)b * NK + k) * NO;
            if (ACCUM) {
#pragma unroll
                for (int o = 0; o < NO; o++) av[o] += g_a[base + o];
            }
#pragma unroll
            for (int o = 0; o < NO; o++) g_a[base + o] = av[o];

            float pr[NO];
            if (mask_at(mraw, (size_t)b * NK + k)) {
#pragma unroll
                for (int o = 0; o < NO; o++) pr[o] = 1.f / 6.f;
            } else {
                float m = av[0];
#pragma unroll
                for (int o = 1; o < NO; o++) m = fmaxf(m, av[o]);
                float ssum = 0.f;
#pragma unroll
                for (int o = 0; o < NO; o++) { pr[o] = expf(av[o] - m); ssum += pr[o]; }
                float inv = 1.f / ssum;
#pragma unroll
                for (int o = 0; o < NO; o++) pr[o] *= inv;
            }
#pragma unroll
            for (int o = 0; o < NO; o++) {
                g_p[base + o] = pr[o];
                sp[warp * 2 + ki][o] = pr[o];
            }
        }
    }
    __syncthreads();

    // phase 2: pu += p^T u over this block's 16 k rows; thread owns 4 d's
    {
        const float4* up4 = (const float4*)(u + ((size_t)b * NK + kb) * ND) + threadIdx.x;
        float4 acc[NO];
#pragma unroll
        for (int o = 0; o < NO; o++) acc[o] = make_float4(0.f, 0.f, 0.f, 0.f);
#pragma unroll 4
        for (int kk = 0; kk < 16; kk++) {
            float4 uv = up4[kk * (ND / 4)];
#pragma unroll
            for (int o = 0; o < NO; o++) {
                float pk = sp[kk][o];
                acc[o].x += pk * uv.x; acc[o].y += pk * uv.y;
                acc[o].z += pk * uv.z; acc[o].w += pk * uv.w;
            }
        }
#pragma unroll
        for (int o = 0; o < NO; o++) {
            float* dst = &g_pu[((size_t)b * NO + o) * ND + threadIdx.x * 4];
            atomicAdd(dst + 0, acc[o].x);
            atomicAdd(dst + 1, acc[o].y);
            atomicAdd(dst + 2, acc[o].z);
            atomicAdd(dst + 3, acc[o].w);
        }
    }
}

// ---------------------------------------------------------------------------
// probs broadcast: probs[b,l,k,o] = p[b,k,o].  grid (NB, NL/16), block 256
__global__ void k_out_p(float4* __restrict__ outp) {
    __shared__ float4 spp[NK * NO / 4];  // 1536 float4 = 24 KB
    int b  = blockIdx.x;
    int lb = blockIdx.y * 16;
    const float4* psrc = (const float4*)(g_p + (size_t)b * NK * NO);
    for (int i = threadIdx.x; i < 1536; i += 256) spp[i] = psrc[i];
    __syncthreads();
    for (int l = 0; l < 16; l++) {
        float4* dst = outp + ((size_t)b * NL + lb + l) * 1536;
#pragma unroll 2
        for (int i = threadIdx.x; i < 1536; i += 256) dst[i] = spp[i];
    }
}

// outputs_v broadcast: squash(S) fused. grid (NB, NL/16), block 256
__global__ void k_out_v(float4* __restrict__ outv) {
    __shared__ __align__(16) float sv[NO * NE];  // 768 floats
    __shared__ float sfac[NO];
    int b  = blockIdx.x;
    int lb = blockIdx.y * 16;
    int wid = threadIdx.x >> 5, lane = threadIdx.x & 31;

    for (int i = threadIdx.x; i < NO * NE; i += 256)
        sv[i] = g_S[(size_t)b * NO * NE + i];
    __syncthreads();

    if (wid < NO) {
        float sq = 0.f;
#pragma unroll
        for (int j = 0; j < 4; j++) {
            float x = sv[wid * NE + lane + 32 * j];
            sq += x * x;
        }
#pragma unroll
        for (int off = 16; off; off >>= 1) sq += __shfl_xor_sync(0xffffffffu, sq, off);
        if (lane == 0) sfac[wid] = sq / (1.f + sq) / (sqrtf(sq) + 1e-8f);
    }
    __syncthreads();
    for (int i = threadIdx.x; i < NO * NE; i += 256)
        sv[i] *= sfac[i >> 7];
    __syncthreads();

    const float4* sv4 = (const float4*)sv;
    for (int idx = threadIdx.x; idx < 16 * 192; idx += 256) {
        int l = idx / 192, c = idx % 192;
        outv[((size_t)b * NL + lb + l) * 192 + c] = sv4[c];
    }
}

// ---------------------------------------------------------------------------
extern "C" void kernel_launch(void* const* d_in, const int* in_sizes, int n_in,
                              void* d_out, int out_size) {
    const float*         u    = (const float*)d_in[0];
    // d_in[1] = context_sequence: unused (result is independent of L content)
    const float*         W    = (const float*)d_in[2];
    const unsigned char* mask = (const unsigned char*)d_in[3];

    float* out   = (float*)d_out;
    float4* outv = (float4*)out;                               // [B,L,O,E]
    float4* outp = (float4*)(out + (size_t)NB * NL * NO * NE); // [B,L,K,O]

    dim3 b256(256);
    dim3 gCS(NB, 32);
    dim3 gS(NO, ND / 16);
    dim3 gWv(NO, ND / 8);
    dim3 gAP(NB, NK / 16);
    dim3 gOUT(NB, NL / 16);

    // iteration 0: uniform p -> colsum shortcut
    k_prolog<<<192, b256>>>(mask);
    k_colsum<<<gCS, b256>>>(u);
    k_S<1><<<gS, 128>>>(W);
    k_WvSq<<<gWv, b256>>>(W);                   // v0 -> Wv0; zero pu
    k_apu<0><<<gAP, b256>>>(u, mask);           // a=u.Wv0, p1, pu1; zero S

    // iteration 1
    k_S<0><<<gS, 128>>>(W);
    k_WvSq<<<gWv, b256>>>(W);                   // v1 -> Wv1; zero pu
    k_apu<1><<<gAP, b256>>>(u, mask);           // a+=u.Wv1, p2, pu2; zero S

    // iteration 2 (final): S2 then squash+v broadcast, then p broadcast
    k_S<0><<<gS, 128>>>(W);
    k_out_v<<<gOUT, b256>>>(outv);
    k_out_p<<<gOUT, b256>>>(outp);

    (void)in_sizes; (void)n_in; (void)out_size;
}

// round 13
// speedup vs baseline: 1.4512x; 1.4512x over previous
#include <cuda_runtime.h>
#include <math.h>

// Problem constants
#define NB 8
#define NK 1024
#define NL 1024
#define ND 1024
#define NO 6
#define NE 128

// Scratch (tiny): everything l-independent
__device__ __align__(16) float g_S [NB*NO*NE];   // raw vote sum   [b,o,e]
__device__ __align__(16) float g_Wv[NB*NO*ND];   // W @ v          [b,o,d]
__device__ __align__(16) float g_a [NB*NK*NO];   // logits         [b,k,o]
__device__ __align__(16) float g_p [NB*NK*NO];   // probs          [b,k,o]
__device__ __align__(16) float g_pu[NB*NO*ND];   // p^T @ u        [b,o,d]
__device__ int g_mask_is_u8;                     // mask dtype flag

// ---------------------------------------------------------------------------
// Prolog: zero g_pu & g_S, detect mask dtype.
__global__ void k_prolog(const unsigned char* __restrict__ mraw) {
    int i = blockIdx.x * 256 + threadIdx.x;
    if (i < NB*NO*ND) g_pu[i] = 0.f;
    if (i < NB*NO*NE) g_S[i]  = 0.f;
    if (blockIdx.x == 0 && threadIdx.x == 0) {
        int u8 = 0;
        for (int j = 0; j < 256; j++)
            if ((j & 3) != 0 && mraw[j] != 0) u8 = 1;
        g_mask_is_u8 = u8;
    }
}

__device__ __forceinline__ int mask_at(const unsigned char* mraw, size_t idx) {
    if (g_mask_is_u8) return mraw[idx] != 0;
    return ((const int*)mraw)[idx] != 0;
}

// ---------------------------------------------------------------------------
// Iteration-0 shortcut: p0 = 1/6 uniform, so pu0[b,o,d] = (1/6)*sum_k u —
// o-independent. colsum into g_pu[b][0][:]. float4: thread owns 4 d's.
// grid (NB, 32) = 256 blocks, block 256; k-chunk = 32.
__global__ void k_colsum(const float* __restrict__ u) {
    int b  = blockIdx.x;
    int kb = blockIdx.y * 32;
    const float4* up4 = (const float4*)(u + ((size_t)b * NK + kb) * ND) + threadIdx.x;
    float4 acc = make_float4(0.f, 0.f, 0.f, 0.f);
#pragma unroll 8
    for (int kk = 0; kk < 32; kk++) {
        float4 uv = up4[kk * (ND / 4)];
        acc.x += uv.x; acc.y += uv.y; acc.z += uv.z; acc.w += uv.w;
    }
    float* dst = &g_pu[(size_t)b * NO * ND + threadIdx.x * 4];
    atomicAdd(dst + 0, acc.x);
    atomicAdd(dst + 1, acc.y);
    atomicAdd(dst + 2, acc.z);
    atomicAdd(dst + 3, acc.w);
}

// ---------------------------------------------------------------------------
// S[b,o,e] += sum_{d in 16-chunk} pu[b,o,d] * W[o,d,e] for all 8 b at once.
// FIRST: read o-independent colsum (o=0 row) scaled by 1/6.
// grid (NO, ND/16), block 128.
template <int FIRST>
__global__ void k_S(const float* __restrict__ W) {
    __shared__ float spu[NB][16];
    int o  = blockIdx.x;
    int dc = blockIdx.y * 16;
    int e  = threadIdx.x;

    {   // 128 threads load exactly 128 entries
        int b = threadIdx.x >> 4, dd = threadIdx.x & 15;
        float v = FIRST ? g_pu[(size_t)b * NO * ND + dc + dd] * (1.f / 6.f)
                        : g_pu[((size_t)b * NO + o) * ND + dc + dd];
        spu[b][dd] = v;
    }
    __syncthreads();

    float acc[NB];
#pragma unroll
    for (int b = 0; b < NB; b++) acc[b] = 0.f;

    const float* Wo = W + ((size_t)o * ND + dc) * NE + e;
#pragma unroll
    for (int dd = 0; dd < 16; dd++) {
        float w = Wo[(size_t)dd * NE];
#pragma unroll
        for (int b = 0; b < NB; b++) acc[b] += spu[b][dd] * w;
    }
#pragma unroll
    for (int b = 0; b < NB; b++)
        atomicAdd(&g_S[((size_t)b * NO + o) * NE + e], acc[b]);
}

// ---------------------------------------------------------------------------
// Fused squash + Wv: v = squash(S) per-block, then Wv[b,o,d] =
// sum_e W[o,d,e]*v[b,o,e] for all 8 b. float4 W + v loads.
// Also zeroes g_pu for the next k_apu (768 blocks x 64 floats).
// grid (NO, ND/8), block 256 = 8 warps (warp = one d)
__global__ void k_WvSq(const float* __restrict__ W) {
    __shared__ __align__(16) float sv[NB][NE];   // 4 KB
    __shared__ float sfac[NB];
    int o = blockIdx.x;
    int wid = threadIdx.x >> 5, lane = threadIdx.x & 31;

    // zero g_pu slice: 49152 / 768 blocks = 64 floats per block
    {
        int slice = blockIdx.x * (ND / 8) + blockIdx.y;   // 0..767
        if (threadIdx.x < 64) g_pu[(size_t)slice * 64 + threadIdx.x] = 0.f;
    }

    for (int i = threadIdx.x; i < NB * NE; i += 256)
        sv[i >> 7][i & 127] = g_S[((size_t)(i >> 7) * NO + o) * NE + (i & 127)];
    __syncthreads();

    // warp w computes squash factor for b=w
    {
        float sq = 0.f;
#pragma unroll
        for (int j = 0; j < 4; j++) {
            float x = sv[wid][lane + 32 * j];
            sq += x * x;
        }
#pragma unroll
        for (int off = 16; off; off >>= 1) sq += __shfl_xor_sync(0xffffffffu, sq, off);
        if (lane == 0) sfac[wid] = sq / (1.f + sq) / (sqrtf(sq) + 1e-8f);
    }
    __syncthreads();
    for (int i = threadIdx.x; i < NB * NE; i += 256)
        sv[i >> 7][i & 127] *= sfac[i >> 7];
    __syncthreads();

    int d = blockIdx.y * 8 + wid;
    const float4* Wrow4 = (const float4*)(W + ((size_t)o * ND + d) * NE);
    float4 wv = Wrow4[lane];

#pragma unroll
    for (int b = 0; b < NB; b++) {
        float4 vv = ((const float4*)sv[b])[lane];
        float s = wv.x * vv.x + wv.y * vv.y + wv.z * vv.z + wv.w * vv.w;
#pragma unroll
        for (int off = 16; off; off >>= 1) s += __shfl_xor_sync(0xffffffffu, s, off);
        if (lane == 0) g_Wv[((size_t)b * NO + o) * ND + d] = s;
    }
}

// ---------------------------------------------------------------------------
// Fused agreement + softmax + pu-accumulation (float4 loads):
//  phase 1: a[b,k,o] (+)= sum_d u[b,k,d]*Wv[b,o,d]; p = masked softmax
//  phase 2: pu[b,o,d] += sum_{k in block} p[k,o]*u[b,k,d]  (u hot in L1/L2)
// Also zeroes g_S slices for the next k_S.
// grid (NB, NK/16) = 512 blocks, block 256 = 8 warps, each warp does 2 k's.
template <int ACCUM>
__global__ void k_apu(const float* __restrict__ u,
                      const unsigned char* __restrict__ mraw) {
    __shared__ __align__(16) float sWv[NO * ND];  // 24 KB
    __shared__ float sp[16][NO];
    int b  = blockIdx.x;
    int kb = blockIdx.y * 16;

    // zero g_S slice: 6144 / 512 blocks = 12 floats each
    {
        int slice = blockIdx.x * 64 + blockIdx.y;   // 0..511
        if (threadIdx.x < 12) g_S[(size_t)slice * 12 + threadIdx.x] = 0.f;
    }

    for (int i = threadIdx.x; i < NO * ND; i += 256)
        sWv[i] = g_Wv[(size_t)b * NO * ND + i];
    __syncthreads();

    int warp = threadIdx.x >> 5, lane = threadIdx.x & 31;

    for (int ki = 0; ki < 2; ki++) {
        int k = kb + warp * 2 + ki;
        const float4* urow4 = (const float4*)(u + ((size_t)b * NK + k) * ND);
        float av[NO];
#pragma unroll
        for (int o = 0; o < NO; o++) av[o] = 0.f;
#pragma unroll
        for (int j = 0; j < 8; j++) {
            float4 uv = urow4[lane + 32 * j];
            int d0 = 4 * lane + 128 * j;
#pragma unroll
            for (int o = 0; o < NO; o++) {
                float4 wv = *(const float4*)&sWv[o * ND + d0];
                av[o] += uv.x * wv.x + uv.y * wv.y + uv.z * wv.z + uv.w * wv.w;
            }
        }
#pragma unroll
        for (int off = 16; off; off >>= 1) {
#pragma unroll
            for (int o = 0; o < NO; o++)
                av[o] += __shfl_xor_sync(0xffffffffu, av[o], off);
        }
        if (lane == 0) {
            size_t base = ((size_t)b * NK + k) * NO;
            if (ACCUM) {
#pragma unroll
                for (int o = 0; o < NO; o++) av[o] += g_a[base + o];
            }
#pragma unroll
            for (int o = 0; o < NO; o++) g_a[base + o] = av[o];

            float pr[NO];
            if (mask_at(mraw, (size_t)b * NK + k)) {
#pragma unroll
                for (int o = 0; o < NO; o++) pr[o] = 1.f / 6.f;
            } else {
                float m = av[0];
#pragma unroll
                for (int o = 1; o < NO; o++) m = fmaxf(m, av[o]);
                float ssum = 0.f;
#pragma unroll
                for (int o = 0; o < NO; o++) { pr[o] = expf(av[o] - m); ssum += pr[o]; }
                float inv = 1.f / ssum;
#pragma unroll
                for (int o = 0; o < NO; o++) pr[o] *= inv;
            }
#pragma unroll
            for (int o = 0; o < NO; o++) {
                g_p[base + o] = pr[o];
                sp[warp * 2 + ki][o] = pr[o];
            }
        }
    }
    __syncthreads();

    // phase 2: pu += p^T u over this block's 16 k rows; thread owns 4 d's
    {
        const float4* up4 = (const float4*)(u + ((size_t)b * NK + kb) * ND) + threadIdx.x;
        float4 acc[NO];
#pragma unroll
        for (int o = 0; o < NO; o++) acc[o] = make_float4(0.f, 0.f, 0.f, 0.f);
#pragma unroll 4
        for (int kk = 0; kk < 16; kk++) {
            float4 uv = up4[kk * (ND / 4)];
#pragma unroll
            for (int o = 0; o < NO; o++) {
                float pk = sp[kk][o];
                acc[o].x += pk * uv.x; acc[o].y += pk * uv.y;
                acc[o].z += pk * uv.z; acc[o].w += pk * uv.w;
            }
        }
#pragma unroll
        for (int o = 0; o < NO; o++) {
            float* dst = &g_pu[((size_t)b * NO + o) * ND + threadIdx.x * 4];
            atomicAdd(dst + 0, acc[o].x);
            atomicAdd(dst + 1, acc[o].y);
            atomicAdd(dst + 2, acc[o].z);
            atomicAdd(dst + 3, acc[o].w);
        }
    }
}

// ---------------------------------------------------------------------------
// Fused final output: squash(S) + broadcast BOTH outputs over L.
// outputs_v[b,l,o,e] = squash(S)[b,o,e]; probs[b,l,k,o] = p[b,k,o].
// grid (NB, NL/16), block 256  (R10-proven shape)
__global__ void k_out(float4* __restrict__ outv, float4* __restrict__ outp) {
    __shared__ float4 spp[NK * NO / 4];          // 1536 float4 = 24 KB
    __shared__ __align__(16) float sv[NO * NE];  // 768 floats
    __shared__ float sfac[NO];
    int b  = blockIdx.x;
    int lb = blockIdx.y * 16;
    int wid = threadIdx.x >> 5, lane = threadIdx.x & 31;

    // stage p[b]
    const float4* psrc = (const float4*)(g_p + (size_t)b * NK * NO);
    for (int i = threadIdx.x; i < 1536; i += 256) spp[i] = psrc[i];

    // stage S[b] and squash
    for (int i = threadIdx.x; i < NO * NE; i += 256)
        sv[i] = g_S[(size_t)b * NO * NE + i];
    __syncthreads();

    if (wid < NO) {
        float sq = 0.f;
#pragma unroll
        for (int j = 0; j < 4; j++) {
            float x = sv[wid * NE + lane + 32 * j];
            sq += x * x;
        }
#pragma unroll
        for (int off = 16; off; off >>= 1) sq += __shfl_xor_sync(0xffffffffu, sq, off);
        if (lane == 0) sfac[wid] = sq / (1.f + sq) / (sqrtf(sq) + 1e-8f);
    }
    __syncthreads();
    for (int i = threadIdx.x; i < NO * NE; i += 256)
        sv[i] *= sfac[i >> 7];
    __syncthreads();

    // write outputs_v: 16 l x 192 float4
    const float4* sv4 = (const float4*)sv;
    for (int idx = threadIdx.x; idx < 16 * 192; idx += 256) {
        int l = idx / 192, c = idx % 192;
        outv[((size_t)b * NL + lb + l) * 192 + c] = sv4[c];
    }

    // write probs: 16 l x 1536 float4
    for (int l = 0; l < 16; l++) {
        float4* dst = outp + ((size_t)b * NL + lb + l) * 1536;
#pragma unroll 2
        for (int i = threadIdx.x; i < 1536; i += 256) dst[i] = spp[i];
    }
}

// ---------------------------------------------------------------------------
extern "C" void kernel_launch(void* const* d_in, const int* in_sizes, int n_in,
                              void* d_out, int out_size) {
    const float*         u    = (const float*)d_in[0];
    // d_in[1] = context_sequence: unused (result is independent of L content)
    const float*         W    = (const float*)d_in[2];
    const unsigned char* mask = (const unsigned char*)d_in[3];

    float* out   = (float*)d_out;
    float4* outv = (float4*)out;                               // [B,L,O,E]
    float4* outp = (float4*)(out + (size_t)NB * NL * NO * NE); // [B,L,K,O]

    dim3 b256(256);
    dim3 gCS(NB, 32);
    dim3 gS(NO, ND / 16);
    dim3 gWv(NO, ND / 8);
    dim3 gAP(NB, NK / 16);
    dim3 gOUT(NB, NL / 16);

    // iteration 0: uniform p -> colsum shortcut
    k_prolog<<<192, b256>>>(mask);
    k_colsum<<<gCS, b256>>>(u);
    k_S<1><<<gS, 128>>>(W);
    k_WvSq<<<gWv, b256>>>(W);                   // v0 -> Wv0; zero pu
    k_apu<0><<<gAP, b256>>>(u, mask);           // a=u.Wv0, p1, pu1; zero S

    // iteration 1
    k_S<0><<<gS, 128>>>(W);
    k_WvSq<<<gWv, b256>>>(W);                   // v1 -> Wv1; zero pu
    k_apu<1><<<gAP, b256>>>(u, mask);           // a+=u.Wv1, p2, pu2; zero S

    // iteration 2 (final): S2 then fused squash + both output broadcasts
    k_S<0><<<gS, 128>>>(W);
    k_out<<<gOUT, b256>>>(outv, outp);

    (void)in_sizes; (void)n_in; (void)out_size;
}

// round 14
// speedup vs baseline: 1.6263x; 1.1206x over previous
#include <cuda_runtime.h>
#include <math.h>

// Problem constants
#define NB 8
#define NK 1024
#define NL 1024
#define ND 1024
#define NO 6
#define NE 128

// Scratch (tiny): everything l-independent
__device__ __align__(16) float g_S [NB*NO*NE];   // raw vote sum   [b,o,e]
__device__ __align__(16) float g_Wv[NB*NO*ND];   // W @ v          [b,o,d]
__device__ __align__(16) float g_a [NB*NK*NO];   // logits         [b,k,o]
__device__ __align__(16) float g_p [NB*NK*NO];   // probs          [b,k,o]
__device__ __align__(16) float g_pu[NB*NO*ND];   // p^T @ u        [b,o,d]
__device__ int g_mask_is_u8;                     // mask dtype flag

// ---------------------------------------------------------------------------
// Prolog: zero g_pu & g_S, detect mask dtype.
__global__ void k_prolog(const unsigned char* __restrict__ mraw) {
    int i = blockIdx.x * 256 + threadIdx.x;
    if (i < NB*NO*ND) g_pu[i] = 0.f;
    if (i < NB*NO*NE) g_S[i]  = 0.f;
    if (blockIdx.x == 0 && threadIdx.x == 0) {
        int u8 = 0;
        for (int j = 0; j < 256; j++)
            if ((j & 3) != 0 && mraw[j] != 0) u8 = 1;
        g_mask_is_u8 = u8;
    }
}

__device__ __forceinline__ int mask_at(const unsigned char* mraw, size_t idx) {
    if (g_mask_is_u8) return mraw[idx] != 0;
    return ((const int*)mraw)[idx] != 0;
}

// ---------------------------------------------------------------------------
// Iteration-0 shortcut: p0 = 1/6 uniformly, so pu0[b,o,d] = (1/6)*sum_k u —
// o-independent. Compute colsum into g_pu[b][o=0][:].
// grid (NB, ND/256, 16), block 256   (R10-proven scalar shape)
__global__ void k_colsum(const float* __restrict__ u) {
    int b  = blockIdx.x;
    int d  = blockIdx.y * 256 + threadIdx.x;
    int kb = blockIdx.z * 64;
    const float* up = u + ((size_t)b * NK + kb) * ND + d;
    float acc = 0.f;
#pragma unroll 8
    for (int kk = 0; kk < 64; kk++) acc += up[(size_t)kk * ND];
    atomicAdd(&g_pu[(size_t)b * NO * ND + d], acc);
}

// ---------------------------------------------------------------------------
// S[b,o,e] += sum_{d in 16-chunk} pu[b,o,d] * W[o,d,e] for all 8 b at once.
// FIRST: read o-independent colsum (o=0 row) scaled by 1/6.
// grid (NO, ND/16), block 128.
template <int FIRST>
__global__ void k_S(const float* __restrict__ W) {
    __shared__ float spu[NB][16];
    int o  = blockIdx.x;
    int dc = blockIdx.y * 16;
    int e  = threadIdx.x;

    {   // 128 threads load exactly 128 entries
        int b = threadIdx.x >> 4, dd = threadIdx.x & 15;
        float v = FIRST ? g_pu[(size_t)b * NO * ND + dc + dd] * (1.f / 6.f)
                        : g_pu[((size_t)b * NO + o) * ND + dc + dd];
        spu[b][dd] = v;
    }
    __syncthreads();

    float acc[NB];
#pragma unroll
    for (int b = 0; b < NB; b++) acc[b] = 0.f;

    const float* Wo = W + ((size_t)o * ND + dc) * NE + e;
#pragma unroll
    for (int dd = 0; dd < 16; dd++) {
        float w = Wo[(size_t)dd * NE];
#pragma unroll
        for (int b = 0; b < NB; b++) acc[b] += spu[b][dd] * w;
    }
#pragma unroll
    for (int b = 0; b < NB; b++)
        atomicAdd(&g_S[((size_t)b * NO + o) * NE + e], acc[b]);
}

// ---------------------------------------------------------------------------
// Fused squash + Wv: v = squash(S) per-block, then Wv[b,o,d] =
// sum_e W[o,d,e]*v[b,o,e] for all 8 b. float4 W + v loads (ncu: 8.3 vs 9.1us).
// Also zeroes g_pu for the next k_apu (768 blocks x 64 floats).
// grid (NO, ND/8), block 256 = 8 warps (warp = one d)
__global__ void k_WvSq(const float* __restrict__ W) {
    __shared__ __align__(16) float sv[NB][NE];   // 4 KB
    __shared__ float sfac[NB];
    int o = blockIdx.x;
    int wid = threadIdx.x >> 5, lane = threadIdx.x & 31;

    // zero g_pu slice: 49152 / 768 blocks = 64 floats per block
    {
        int slice = blockIdx.x * (ND / 8) + blockIdx.y;   // 0..767
        if (threadIdx.x < 64) g_pu[(size_t)slice * 64 + threadIdx.x] = 0.f;
    }

    for (int i = threadIdx.x; i < NB * NE; i += 256)
        sv[i >> 7][i & 127] = g_S[((size_t)(i >> 7) * NO + o) * NE + (i & 127)];
    __syncthreads();

    // warp w computes squash factor for b=w
    {
        float sq = 0.f;
#pragma unroll
        for (int j = 0; j < 4; j++) {
            float x = sv[wid][lane + 32 * j];
            sq += x * x;
        }
#pragma unroll
        for (int off = 16; off; off >>= 1) sq += __shfl_xor_sync(0xffffffffu, sq, off);
        if (lane == 0) sfac[wid] = sq / (1.f + sq) / (sqrtf(sq) + 1e-8f);
    }
    __syncthreads();
    for (int i = threadIdx.x; i < NB * NE; i += 256)
        sv[i >> 7][i & 127] *= sfac[i >> 7];
    __syncthreads();

    int d = blockIdx.y * 8 + wid;
    const float4* Wrow4 = (const float4*)(W + ((size_t)o * ND + d) * NE);
    float4 wv = Wrow4[lane];

#pragma unroll
    for (int b = 0; b < NB; b++) {
        float4 vv = ((const float4*)sv[b])[lane];
        float s = wv.x * vv.x + wv.y * vv.y + wv.z * vv.z + wv.w * vv.w;
#pragma unroll
        for (int off = 16; off; off >>= 1) s += __shfl_xor_sync(0xffffffffu, s, off);
        if (lane == 0) g_Wv[((size_t)b * NO + o) * ND + d] = s;
    }
}

// ---------------------------------------------------------------------------
// Fused agreement + softmax + pu-accumulation (R10-proven scalar body):
//  phase 1: a[b,k,o] (+)= sum_d u[b,k,d]*Wv[b,o,d]; p = masked softmax
//  phase 2: pu[b,o,d] += sum_{k in block} p[k,o]*u[b,k,d]  (u hot in L1/L2)
// Also zeroes g_S slices for the next k_S.
// grid (NB, NK/16) = 512 blocks, block 256 = 8 warps, each warp does 2 k's.
template <int ACCUM>
__global__ void k_apu(const float* __restrict__ u,
                      const unsigned char* __restrict__ mraw) {
    __shared__ float sWv[NO * ND];  // 24 KB
    __shared__ float sp[16][NO];
    int b  = blockIdx.x;
    int kb = blockIdx.y * 16;

    // zero g_S slice: 6144 / 512 blocks = 12 floats each
    {
        int slice = blockIdx.x * 64 + blockIdx.y;   // 0..511
        if (threadIdx.x < 12) g_S[(size_t)slice * 12 + threadIdx.x] = 0.f;
    }

    for (int i = threadIdx.x; i < NO * ND; i += 256)
        sWv[i] = g_Wv[(size_t)b * NO * ND + i];
    __syncthreads();

    int warp = threadIdx.x >> 5, lane = threadIdx.x & 31;

    for (int ki = 0; ki < 2; ki++) {
        int k = kb + warp * 2 + ki;
        const float* urow = u + ((size_t)b * NK + k) * ND;
        float a0 = 0, a1 = 0, a2 = 0, a3 = 0, a4 = 0, a5 = 0;
#pragma unroll 4
        for (int j = 0; j < 32; j++) {
            int d = lane + 32 * j;
            float uv = urow[d];
            a0 += uv * sWv[d];
            a1 += uv * sWv[ND + d];
            a2 += uv * sWv[2 * ND + d];
            a3 += uv * sWv[3 * ND + d];
            a4 += uv * sWv[4 * ND + d];
            a5 += uv * sWv[5 * ND + d];
        }
#pragma unroll
        for (int off = 16; off; off >>= 1) {
            a0 += __shfl_xor_sync(0xffffffffu, a0, off);
            a1 += __shfl_xor_sync(0xffffffffu, a1, off);
            a2 += __shfl_xor_sync(0xffffffffu, a2, off);
            a3 += __shfl_xor_sync(0xffffffffu, a3, off);
            a4 += __shfl_xor_sync(0xffffffffu, a4, off);
            a5 += __shfl_xor_sync(0xffffffffu, a5, off);
        }
        if (lane == 0) {
            float av[NO] = {a0, a1, a2, a3, a4, a5};
            size_t base = ((size_t)b * NK + k) * NO;
            if (ACCUM) {
#pragma unroll
                for (int o = 0; o < NO; o++) av[o] += g_a[base + o];
            }
#pragma unroll
            for (int o = 0; o < NO; o++) g_a[base + o] = av[o];

            float pr[NO];
            if (mask_at(mraw, (size_t)b * NK + k)) {
#pragma unroll
                for (int o = 0; o < NO; o++) pr[o] = 1.f / 6.f;
            } else {
                float m = av[0];
#pragma unroll
                for (int o = 1; o < NO; o++) m = fmaxf(m, av[o]);
                float ssum = 0.f;
#pragma unroll
                for (int o = 0; o < NO; o++) { pr[o] = expf(av[o] - m); ssum += pr[o]; }
                float inv = 1.f / ssum;
#pragma unroll
                for (int o = 0; o < NO; o++) pr[o] *= inv;
            }
#pragma unroll
            for (int o = 0; o < NO; o++) {
                g_p[base + o] = pr[o];
                sp[warp * 2 + ki][o] = pr[o];
            }
        }
    }
    __syncthreads();

    // phase 2: pu accumulation over this block's 16 k rows (hot in L1/L2)
#pragma unroll
    for (int dj = 0; dj < 4; dj++) {
        int d = dj * 256 + threadIdx.x;
        const float* ucol = u + ((size_t)b * NK + kb) * ND + d;
        float acc[NO];
#pragma unroll
        for (int o = 0; o < NO; o++) acc[o] = 0.f;
#pragma unroll 4
        for (int kk = 0; kk < 16; kk++) {
            float uv = ucol[(size_t)kk * ND];
#pragma unroll
            for (int o = 0; o < NO; o++) acc[o] += sp[kk][o] * uv;
        }
#pragma unroll
        for (int o = 0; o < NO; o++)
            atomicAdd(&g_pu[((size_t)b * NO + o) * ND + d], acc[o]);
    }
}

// ---------------------------------------------------------------------------
// Fused final output: squash(S) + broadcast BOTH outputs over L.
// outputs_v[b,l,o,e] = squash(S)[b,o,e]; probs[b,l,k,o] = p[b,k,o].
// grid (NB, NL/16), block 256  (R10-proven shape)
__global__ void k_out(float4* __restrict__ outv, float4* __restrict__ outp) {
    __shared__ float4 spp[NK * NO / 4];          // 1536 float4 = 24 KB
    __shared__ __align__(16) float sv[NO * NE];  // 768 floats
    __shared__ float sfac[NO];
    int b  = blockIdx.x;
    int lb = blockIdx.y * 16;
    int wid = threadIdx.x >> 5, lane = threadIdx.x & 31;

    // stage p[b]
    const float4* psrc = (const float4*)(g_p + (size_t)b * NK * NO);
    for (int i = threadIdx.x; i < 1536; i += 256) spp[i] = psrc[i];

    // stage S[b] and squash
    for (int i = threadIdx.x; i < NO * NE; i += 256)
        sv[i] = g_S[(size_t)b * NO * NE + i];
    __syncthreads();

    if (wid < NO) {
        float sq = 0.f;
#pragma unroll
        for (int j = 0; j < 4; j++) {
            float x = sv[wid * NE + lane + 32 * j];
            sq += x * x;
        }
#pragma unroll
        for (int off = 16; off; off >>= 1) sq += __shfl_xor_sync(0xffffffffu, sq, off);
        if (lane == 0) sfac[wid] = sq / (1.f + sq) / (sqrtf(sq) + 1e-8f);
    }
    __syncthreads();
    for (int i = threadIdx.x; i < NO * NE; i += 256)
        sv[i] *= sfac[i >> 7];
    __syncthreads();

    // write outputs_v: 16 l x 192 float4
    const float4* sv4 = (const float4*)sv;
    for (int idx = threadIdx.x; idx < 16 * 192; idx += 256) {
        int l = idx / 192, c = idx % 192;
        outv[((size_t)b * NL + lb + l) * 192 + c] = sv4[c];
    }

    // write probs: 16 l x 1536 float4
    for (int l = 0; l < 16; l++) {
        float4* dst = outp + ((size_t)b * NL + lb + l) * 1536;
#pragma unroll 2
        for (int i = threadIdx.x; i < 1536; i += 256) dst[i] = spp[i];
    }
}

// ---------------------------------------------------------------------------
extern "C" void kernel_launch(void* const* d_in, const int* in_sizes, int n_in,
                              void* d_out, int out_size) {
    const float*         u    = (const float*)d_in[0];
    // d_in[1] = context_sequence: unused (result is independent of L content)
    const float*         W    = (const float*)d_in[2];
    const unsigned char* mask = (const unsigned char*)d_in[3];

    float* out   = (float*)d_out;
    float4* outv = (float4*)out;                               // [B,L,O,E]
    float4* outp = (float4*)(out + (size_t)NB * NL * NO * NE); // [B,L,K,O]

    dim3 b256(256);
    dim3 gCS(NB, ND / 256, 16);
    dim3 gS(NO, ND / 16);
    dim3 gWv(NO, ND / 8);
    dim3 gAP(NB, NK / 16);
    dim3 gOUT(NB, NL / 16);

    // iteration 0: uniform p -> colsum shortcut
    k_prolog<<<192, b256>>>(mask);
    k_colsum<<<gCS, b256>>>(u);
    k_S<1><<<gS, 128>>>(W);
    k_WvSq<<<gWv, b256>>>(W);                   // v0 -> Wv0; zero pu
    k_apu<0><<<gAP, b256>>>(u, mask);           // a=u.Wv0, p1, pu1; zero S

    // iteration 1
    k_S<0><<<gS, 128>>>(W);
    k_WvSq<<<gWv, b256>>>(W);                   // v1 -> Wv1; zero pu
    k_apu<1><<<gAP, b256>>>(u, mask);           // a+=u.Wv1, p2, pu2; zero S

    // iteration 2 (final): S2 then fused squash + both output broadcasts
    k_S<0><<<gS, 128>>>(W);
    k_out<<<gOUT, b256>>>(outv, outp);

    (void)in_sizes; (void)n_in; (void)out_size;
}

// round 15
// speedup vs baseline: 1.6453x; 1.0117x over previous
#include <cuda_runtime.h>
#include <math.h>

// Problem constants
#define NB 8
#define NK 1024
#define NL 1024
#define ND 1024
#define NO 6
#define NE 128

// Scratch (tiny): everything l-independent
__device__ __align__(16) float g_S [NB*NO*NE];   // raw vote sum   [b,o,e]
__device__ __align__(16) float g_Wv[NB*NO*ND];   // W @ v          [b,o,d]
__device__ __align__(16) float g_a [NB*NK*NO];   // logits         [b,k,o]
__device__ __align__(16) float g_p [NB*NK*NO];   // probs          [b,k,o]
__device__ __align__(16) float g_pu[NB*NO*ND];   // p^T @ u        [b,o,d]
__device__ int g_mask_is_u8;                     // mask dtype flag

// ---------------------------------------------------------------------------
// Prolog: zero g_pu & g_S, detect mask dtype (parallel, one load per thread).
// If mask is int32 (LE), bytes at i%4!=0 over the first 256 bytes are all
// zero (values 0/1); if uint8 0/1 mask, ~half are nonzero.
__global__ void k_prolog(const unsigned char* __restrict__ mraw) {
    int i = blockIdx.x * 256 + threadIdx.x;
    if (i < NB*NO*ND) g_pu[i] = 0.f;
    if (i < NB*NO*NE) g_S[i]  = 0.f;
    if (blockIdx.x == 0) {
        int flag = ((threadIdx.x & 3) != 0 && mraw[threadIdx.x] != 0) ? 1 : 0;
        int u8 = __syncthreads_or(flag);
        if (threadIdx.x == 0) g_mask_is_u8 = u8;
    }
}

__device__ __forceinline__ int mask_at(const unsigned char* mraw, size_t idx) {
    if (g_mask_is_u8) return mraw[idx] != 0;
    return ((const int*)mraw)[idx] != 0;
}

// ---------------------------------------------------------------------------
// Iteration-0 shortcut: p0 = 1/6 uniformly, so pu0[b,o,d] = (1/6)*sum_k u —
// o-independent. Compute colsum into g_pu[b][o=0][:].
// grid (NB, ND/256, 16), block 256   (R10-proven scalar shape)
__global__ void k_colsum(const float* __restrict__ u) {
    int b  = blockIdx.x;
    int d  = blockIdx.y * 256 + threadIdx.x;
    int kb = blockIdx.z * 64;
    const float* up = u + ((size_t)b * NK + kb) * ND + d;
    float acc = 0.f;
#pragma unroll 8
    for (int kk = 0; kk < 64; kk++) acc += up[(size_t)kk * ND];
    atomicAdd(&g_pu[(size_t)b * NO * ND + d], acc);
}

// ---------------------------------------------------------------------------
// S[b,o,e] += sum_{d in 16-chunk} pu[b,o,d] * W[o,d,e] for all 8 b at once.
// FIRST: read o-independent colsum (o=0 row) scaled by 1/6.
// grid (NO, ND/16), block 128.
template <int FIRST>
__global__ void k_S(const float* __restrict__ W) {
    __shared__ float spu[NB][16];
    int o  = blockIdx.x;
    int dc = blockIdx.y * 16;
    int e  = threadIdx.x;

    {   // 128 threads load exactly 128 entries
        int b = threadIdx.x >> 4, dd = threadIdx.x & 15;
        float v = FIRST ? g_pu[(size_t)b * NO * ND + dc + dd] * (1.f / 6.f)
                        : g_pu[((size_t)b * NO + o) * ND + dc + dd];
        spu[b][dd] = v;
    }
    __syncthreads();

    float acc[NB];
#pragma unroll
    for (int b = 0; b < NB; b++) acc[b] = 0.f;

    const float* Wo = W + ((size_t)o * ND + dc) * NE + e;
#pragma unroll
    for (int dd = 0; dd < 16; dd++) {
        float w = Wo[(size_t)dd * NE];
#pragma unroll
        for (int b = 0; b < NB; b++) acc[b] += spu[b][dd] * w;
    }
#pragma unroll
    for (int b = 0; b < NB; b++)
        atomicAdd(&g_S[((size_t)b * NO + o) * NE + e], acc[b]);
}

// ---------------------------------------------------------------------------
// Fused squash + Wv: v = squash(S) per-block, then Wv[b,o,d] =
// sum_e W[o,d,e]*v[b,o,e] for all 8 b. float4 W + v loads.
// Each warp produces TWO d rows (d0, d0+8) to amortize per-block staging.
// Also zeroes g_pu for the next k_apu (384 blocks x 128 floats).
// grid (NO, ND/16) = 384 blocks, block 256 = 8 warps.
__global__ void k_WvSq(const float* __restrict__ W) {
    __shared__ __align__(16) float sv[NB][NE];   // 4 KB
    __shared__ float sfac[NB];
    int o = blockIdx.x;
    int wid = threadIdx.x >> 5, lane = threadIdx.x & 31;

    // zero g_pu slice: 49152 / 384 blocks = 128 floats per block
    {
        int slice = blockIdx.x * (ND / 16) + blockIdx.y;   // 0..383
        if (threadIdx.x < 128) g_pu[(size_t)slice * 128 + threadIdx.x] = 0.f;
    }

    for (int i = threadIdx.x; i < NB * NE; i += 256)
        sv[i >> 7][i & 127] = g_S[((size_t)(i >> 7) * NO + o) * NE + (i & 127)];
    __syncthreads();

    // warp w computes squash factor for b=w
    {
        float sq = 0.f;
#pragma unroll
        for (int j = 0; j < 4; j++) {
            float x = sv[wid][lane + 32 * j];
            sq += x * x;
        }
#pragma unroll
        for (int off = 16; off; off >>= 1) sq += __shfl_xor_sync(0xffffffffu, sq, off);
        if (lane == 0) sfac[wid] = sq / (1.f + sq) / (sqrtf(sq) + 1e-8f);
    }
    __syncthreads();
    for (int i = threadIdx.x; i < NB * NE; i += 256)
        sv[i >> 7][i & 127] *= sfac[i >> 7];
    __syncthreads();

    int d0 = blockIdx.y * 16 + wid;       // first row
    int d1 = d0 + 8;                      // second row
    const float4* Wr0 = (const float4*)(W + ((size_t)o * ND + d0) * NE);
    const float4* Wr1 = (const float4*)(W + ((size_t)o * ND + d1) * NE);
    float4 w0 = Wr0[lane];
    float4 w1 = Wr1[lane];

#pragma unroll
    for (int b = 0; b < NB; b++) {
        float4 vv = ((const float4*)sv[b])[lane];
        float s0 = w0.x * vv.x + w0.y * vv.y + w0.z * vv.z + w0.w * vv.w;
        float s1 = w1.x * vv.x + w1.y * vv.y + w1.z * vv.z + w1.w * vv.w;
#pragma unroll
        for (int off = 16; off; off >>= 1) {
            s0 += __shfl_xor_sync(0xffffffffu, s0, off);
            s1 += __shfl_xor_sync(0xffffffffu, s1, off);
        }
        if (lane == 0) {
            g_Wv[((size_t)b * NO + o) * ND + d0] = s0;
            g_Wv[((size_t)b * NO + o) * ND + d1] = s1;
        }
    }
}

// ---------------------------------------------------------------------------
// Fused agreement + softmax + pu-accumulation (R10-proven scalar body):
//  phase 1: a[b,k,o] (+)= sum_d u[b,k,d]*Wv[b,o,d]; p = masked softmax
//  phase 2: pu[b,o,d] += sum_{k in block} p[k,o]*u[b,k,d]  (u hot in L1/L2)
// Also zeroes g_S slices for the next k_S.
// grid (NB, NK/16) = 512 blocks, block 256 = 8 warps, each warp does 2 k's.
template <int ACCUM>
__global__ void k_apu(const float* __restrict__ u,
                      const unsigned char* __restrict__ mraw) {
    __shared__ float sWv[NO * ND];  // 24 KB
    __shared__ float sp[16][NO];
    int b  = blockIdx.x;
    int kb = blockIdx.y * 16;

    // zero g_S slice: 6144 / 512 blocks = 12 floats each
    {
        int slice = blockIdx.x * 64 + blockIdx.y;   // 0..511
        if (threadIdx.x < 12) g_S[(size_t)slice * 12 + threadIdx.x] = 0.f;
    }

    for (int i = threadIdx.x; i < NO * ND; i += 256)
        sWv[i] = g_Wv[(size_t)b * NO * ND + i];
    __syncthreads();

    int warp = threadIdx.x >> 5, lane = threadIdx.x & 31;

    for (int ki = 0; ki < 2; ki++) {
        int k = kb + warp * 2 + ki;
        const float* urow = u + ((size_t)b * NK + k) * ND;
        float a0 = 0, a1 = 0, a2 = 0, a3 = 0, a4 = 0, a5 = 0;
#pragma unroll 4
        for (int j = 0; j < 32; j++) {
            int d = lane + 32 * j;
            float uv = urow[d];
            a0 += uv * sWv[d];
            a1 += uv * sWv[ND + d];
            a2 += uv * sWv[2 * ND + d];
            a3 += uv * sWv[3 * ND + d];
            a4 += uv * sWv[4 * ND + d];
            a5 += uv * sWv[5 * ND + d];
        }
#pragma unroll
        for (int off = 16; off; off >>= 1) {
            a0 += __shfl_xor_sync(0xffffffffu, a0, off);
            a1 += __shfl_xor_sync(0xffffffffu, a1, off);
            a2 += __shfl_xor_sync(0xffffffffu, a2, off);
            a3 += __shfl_xor_sync(0xffffffffu, a3, off);
            a4 += __shfl_xor_sync(0xffffffffu, a4, off);
            a5 += __shfl_xor_sync(0xffffffffu, a5, off);
        }
        if (lane == 0) {
            float av[NO] = {a0, a1, a2, a3, a4, a5};
            size_t base = ((size_t)b * NK + k) * NO;
            if (ACCUM) {
#pragma unroll
                for (int o = 0; o < NO; o++) av[o] += g_a[base + o];
            }
#pragma unroll
            for (int o = 0; o < NO; o++) g_a[base + o] = av[o];

            float pr[NO];
            if (mask_at(mraw, (size_t)b * NK + k)) {
#pragma unroll
                for (int o = 0; o < NO; o++) pr[o] = 1.f / 6.f;
            } else {
                float m = av[0];
#pragma unroll
                for (int o = 1; o < NO; o++) m = fmaxf(m, av[o]);
                float ssum = 0.f;
#pragma unroll
                for (int o = 0; o < NO; o++) { pr[o] = expf(av[o] - m); ssum += pr[o]; }
                float inv = 1.f / ssum;
#pragma unroll
                for (int o = 0; o < NO; o++) pr[o] *= inv;
            }
#pragma unroll
            for (int o = 0; o < NO; o++) {
                g_p[base + o] = pr[o];
                sp[warp * 2 + ki][o] = pr[o];
            }
        }
    }
    __syncthreads();

    // phase 2: pu accumulation over this block's 16 k rows (hot in L1/L2)
#pragma unroll
    for (int dj = 0; dj < 4; dj++) {
        int d = dj * 256 + threadIdx.x;
        const float* ucol = u + ((size_t)b * NK + kb) * ND + d;
        float acc[NO];
#pragma unroll
        for (int o = 0; o < NO; o++) acc[o] = 0.f;
#pragma unroll 4
        for (int kk = 0; kk < 16; kk++) {
            float uv = ucol[(size_t)kk * ND];
#pragma unroll
            for (int o = 0; o < NO; o++) acc[o] += sp[kk][o] * uv;
        }
#pragma unroll
        for (int o = 0; o < NO; o++)
            atomicAdd(&g_pu[((size_t)b * NO + o) * ND + d], acc[o]);
    }
}

// ---------------------------------------------------------------------------
// Fused final output: squash(S) + broadcast BOTH outputs over L.
// outputs_v[b,l,o,e] = squash(S)[b,o,e]; probs[b,l,k,o] = p[b,k,o].
// grid (NB, NL/16), block 256  (R10-proven shape)
__global__ void k_out(float4* __restrict__ outv, float4* __restrict__ outp) {
    __shared__ float4 spp[NK * NO / 4];          // 1536 float4 = 24 KB
    __shared__ __align__(16) float sv[NO * NE];  // 768 floats
    __shared__ float sfac[NO];
    int b  = blockIdx.x;
    int lb = blockIdx.y * 16;
    int wid = threadIdx.x >> 5, lane = threadIdx.x & 31;

    // stage p[b]
    const float4* psrc = (const float4*)(g_p + (size_t)b * NK * NO);
    for (int i = threadIdx.x; i < 1536; i += 256) spp[i] = psrc[i];

    // stage S[b] and squash
    for (int i = threadIdx.x; i < NO * NE; i += 256)
        sv[i] = g_S[(size_t)b * NO * NE + i];
    __syncthreads();

    if (wid < NO) {
        float sq = 0.f;
#pragma unroll
        for (int j = 0; j < 4; j++) {
            float x = sv[wid * NE + lane + 32 * j];
            sq += x * x;
        }
#pragma unroll
        for (int off = 16; off; off >>= 1) sq += __shfl_xor_sync(0xffffffffu, sq, off);
        if (lane == 0) sfac[wid] = sq / (1.f + sq) / (sqrtf(sq) + 1e-8f);
    }
    __syncthreads();
    for (int i = threadIdx.x; i < NO * NE; i += 256)
        sv[i] *= sfac[i >> 7];
    __syncthreads();

    // write outputs_v: 16 l x 192 float4
    const float4* sv4 = (const float4*)sv;
    for (int idx = threadIdx.x; idx < 16 * 192; idx += 256) {
        int l = idx / 192, c = idx % 192;
        outv[((size_t)b * NL + lb + l) * 192 + c] = sv4[c];
    }

    // write probs: 16 l x 1536 float4
    for (int l = 0; l < 16; l++) {
        float4* dst = outp + ((size_t)b * NL + lb + l) * 1536;
#pragma unroll 2
        for (int i = threadIdx.x; i < 1536; i += 256) dst[i] = spp[i];
    }
}

// ---------------------------------------------------------------------------
extern "C" void kernel_launch(void* const* d_in, const int* in_sizes, int n_in,
                              void* d_out, int out_size) {
    const float*         u    = (const float*)d_in[0];
    // d_in[1] = context_sequence: unused (result is independent of L content)
    const float*         W    = (const float*)d_in[2];
    const unsigned char* mask = (const unsigned char*)d_in[3];

    float* out   = (float*)d_out;
    float4* outv = (float4*)out;                               // [B,L,O,E]
    float4* outp = (float4*)(out + (size_t)NB * NL * NO * NE); // [B,L,K,O]

    dim3 b256(256);
    dim3 gCS(NB, ND / 256, 16);
    dim3 gS(NO, ND / 16);
    dim3 gWv(NO, ND / 16);
    dim3 gAP(NB, NK / 16);
    dim3 gOUT(NB, NL / 16);

    // iteration 0: uniform p -> colsum shortcut
    k_prolog<<<192, b256>>>(mask);
    k_colsum<<<gCS, b256>>>(u);
    k_S<1><<<gS, 128>>>(W);
    k_WvSq<<<gWv, b256>>>(W);                   // v0 -> Wv0; zero pu
    k_apu<0><<<gAP, b256>>>(u, mask);           // a=u.Wv0, p1, pu1; zero S

    // iteration 1
    k_S<0><<<gS, 128>>>(W);
    k_WvSq<<<gWv, b256>>>(W);                   // v1 -> Wv1; zero pu
    k_apu<1><<<gAP, b256>>>(u, mask);           // a+=u.Wv1, p2, pu2; zero S

    // iteration 2 (final): S2 then fused squash + both output broadcasts
    k_S<0><<<gS, 128>>>(W);
    k_out<<<gOUT, b256>>>(outv, outp);

    (void)in_sizes; (void)n_in; (void)out_size;
}